// round 10
// baseline (speedup 1.0000x reference)
#include <cuda_runtime.h>
#include <cuda_fp16.h>
#include <cstdint>

// ============================================================================
// EdgeMLP: out = silu( silu(LN(concat(src,edge) @ W1 + b1)) @ W2 + b2 )
// E rows; in 192 (128 src + 64 edge), hid/out 128.
//
// R10: warp-pair M=32/N=64 tiling (R8 profile: L1 86.7% = B-fragment LDS
// binder; R9 showed occupancy beyond 16 warps/SM unbuyable -> back to 256thr).
//   - pair of warps owns 32 rows; role 0 -> out cols 0..63, role 1 -> 64..127
//   - each B LDS.128 feeds 4 mmas (2 M-tiles x 2 N-tiles): ~2.7x less LDS
//   - LN moments + GEMM1->GEMM2 activations exchanged through small smem
//     buffers with uniform-trip-count loop + __syncthreads (5 per iteration)
//   - A streamed per-kt with a 2-deep register double buffer (R6 lesson: no
//     big live range across GEMMs); acc still 64 regs
//   - keeps: K/N-permuted fragments (LDG.128/STG.128), one-pass LN,
//     tanh.approx silu, fragment-order weights in smem
// ============================================================================

static constexpr float LN_EPS = 1e-5f;

// dynamic smem layout (bytes)
static constexpr int SM_W1F = 0;                       // 12*8*32*16 = 49152
static constexpr int SM_W2F = SM_W1F + 49152;          // 8*8*32*16 = 32768
static constexpr int SM_B1  = SM_W2F + 32768;          // 81920
static constexpr int SM_GM  = SM_B1 + 512;
static constexpr int SM_BT  = SM_GM + 512;
static constexpr int SM_B2  = SM_BT + 512;
static constexpr int SM_PS  = SM_B2 + 512;             // 83968: 4pair*2role*32row*float2 = 2048
static constexpr int SM_A2X = SM_PS + 2048;            // 86016: 4pair*8kt2*32lane*uint4 = 16384
static constexpr int SMEM_BYTES = SM_A2X + 16384;      // 102400

__device__ __forceinline__ uint32_t packh2(float a, float b) {
    __half2 h = __floats2half2_rn(a, b);
    return *reinterpret_cast<uint32_t*>(&h);
}

__device__ __forceinline__ void mma16816(float c[4],
                                         uint32_t a0, uint32_t a1, uint32_t a2, uint32_t a3,
                                         uint32_t b0, uint32_t b1) {
    asm volatile(
        "mma.sync.aligned.m16n8k16.row.col.f32.f16.f16.f32 "
        "{%0,%1,%2,%3}, {%4,%5,%6,%7}, {%8,%9}, {%0,%1,%2,%3};"
        : "+f"(c[0]), "+f"(c[1]), "+f"(c[2]), "+f"(c[3])
        : "r"(a0), "r"(a1), "r"(a2), "r"(a3), "r"(b0), "r"(b1));
}

__device__ __forceinline__ float silu(float x) {
    float hx = 0.5f * x;
    float t;
    asm("tanh.approx.f32 %0, %1;" : "=f"(t) : "f"(hx));
    return fmaf(hx, t, hx);
}

__global__ void __launch_bounds__(256, 2) edge_mlp_kernel(
    const float* __restrict__ src, const float* __restrict__ edg,
    const float* __restrict__ W1, const float* __restrict__ b1,
    const float* __restrict__ gma, const float* __restrict__ bta,
    const float* __restrict__ W2, const float* __restrict__ b2,
    float* __restrict__ out, int E, int n_iter)
{
    extern __shared__ char smem[];
    uint4*  w1f = reinterpret_cast<uint4*>(smem + SM_W1F);
    uint4*  w2f = reinterpret_cast<uint4*>(smem + SM_W2F);
    float*  b1s = reinterpret_cast<float*>(smem + SM_B1);
    float*  gms = reinterpret_cast<float*>(smem + SM_GM);
    float*  bts = reinterpret_cast<float*>(smem + SM_BT);
    float*  b2s = reinterpret_cast<float*>(smem + SM_B2);
    float2* psm = reinterpret_cast<float2*>(smem + SM_PS);
    uint4*  a2x = reinterpret_cast<uint4*>(smem + SM_A2X);

    const int tid  = threadIdx.x;
    const int lane = tid & 31;
    const int wid  = tid >> 5;
    const int q    = lane >> 2;   // 0..7
    const int c4   = lane & 3;    // 0..3
    const int role = wid & 1;     // 0: cols 0..63, 1: cols 64..127
    const int pair = wid >> 1;    // 0..3
    const int nbase = role * 4;   // global n16-pair base for this warp

    // ---- one-time: params + fragment-order weight swizzle (same as R8) ----
    for (int i = tid; i < 128; i += 256) {
        b1s[i] = b1[i];
        gms[i] = gma[i];
        bts[i] = bta[i];
        b2s[i] = b2[i];
    }
    for (int e = tid; e < 12 * 8 * 32; e += 256) {
        int l = e & 31, slot = e >> 5;
        int np = slot & 7, kt = slot >> 3;
        int k = kt * 16 + 4 * (l & 3);
        int qq = l >> 2;
        int n0 = np * 16 + 4 * (qq >> 1) + (qq & 1);
        int n1 = n0 + 2;
        uint4 v;
        v.x = packh2(W1[k * 128 + n0], W1[(k + 1) * 128 + n0]);
        v.y = packh2(W1[(k + 2) * 128 + n0], W1[(k + 3) * 128 + n0]);
        v.z = packh2(W1[k * 128 + n1], W1[(k + 1) * 128 + n1]);
        v.w = packh2(W1[(k + 2) * 128 + n1], W1[(k + 3) * 128 + n1]);
        w1f[e] = v;
    }
    for (int e = tid; e < 8 * 8 * 32; e += 256) {
        int l = e & 31, slot = e >> 5;
        int np = slot & 7, kt = slot >> 3;
        int k = kt * 16 + 4 * (l & 3);
        int qq = l >> 2;
        int n0 = np * 16 + 4 * (qq >> 1) + (qq & 1);
        int n1 = n0 + 2;
        uint4 v;
        v.x = packh2(W2[k * 128 + n0], W2[(k + 1) * 128 + n0]);
        v.y = packh2(W2[(k + 2) * 128 + n0], W2[(k + 3) * 128 + n0]);
        v.z = packh2(W2[k * 128 + n1], W2[(k + 1) * 128 + n1]);
        v.w = packh2(W2[(k + 2) * 128 + n1], W2[(k + 3) * 128 + n1]);
        w2f[e] = v;
    }
    __syncthreads();

    const int pid   = blockIdx.x * 4 + pair;
    const int pstep = gridDim.x * 4;

    for (int it = 0; it < n_iter; it++) {
        const int rbase = (pid + it * pstep) * 32;

        // clamped row offsets (dummy tail iterations load row E-1, store nothing)
        size_t ro[2][2];
        #pragma unroll
        for (int mt = 0; mt < 2; mt++) {
            ro[mt][0] = (size_t)min(rbase + mt * 16 + q,     E - 1);
            ro[mt][1] = (size_t)min(rbase + mt * 16 + q + 8, E - 1);
        }

        // ---- GEMM1: [32x192] @ W1[:,nbase*16 .. +64] -> acc[2 mt][8 nt][4] ----
        float acc[2][8][4];
        #pragma unroll
        for (int mt = 0; mt < 2; mt++)
            #pragma unroll
            for (int nt = 0; nt < 8; nt++) {
                acc[mt][nt][0] = 0.f; acc[mt][nt][1] = 0.f;
                acc[mt][nt][2] = 0.f; acc[mt][nt][3] = 0.f;
            }

        uint32_t afb[2][2][4];  // [buf][mt][4], double-buffered A fragments
        {
            const int kc = 4 * c4;  // kt=0 column
            #pragma unroll
            for (int mt = 0; mt < 2; mt++) {
                float4 v = *reinterpret_cast<const float4*>(src + ro[mt][0] * 128 + kc);
                float4 w = *reinterpret_cast<const float4*>(src + ro[mt][1] * 128 + kc);
                afb[0][mt][0] = packh2(v.x, v.y); afb[0][mt][2] = packh2(v.z, v.w);
                afb[0][mt][1] = packh2(w.x, w.y); afb[0][mt][3] = packh2(w.z, w.w);
            }
        }
        #pragma unroll
        for (int kt = 0; kt < 12; kt++) {
            if (kt + 1 < 12) {
                const int kn = kt + 1;
                const float* bp = (kn < 8) ? src : edg;
                const int pitch = (kn < 8) ? 128 : 64;
                const int kc = ((kn < 8) ? kn * 16 : (kn - 8) * 16) + 4 * c4;
                #pragma unroll
                for (int mt = 0; mt < 2; mt++) {
                    float4 v = *reinterpret_cast<const float4*>(bp + ro[mt][0] * pitch + kc);
                    float4 w = *reinterpret_cast<const float4*>(bp + ro[mt][1] * pitch + kc);
                    afb[kn & 1][mt][0] = packh2(v.x, v.y); afb[kn & 1][mt][2] = packh2(v.z, v.w);
                    afb[kn & 1][mt][1] = packh2(w.x, w.y); afb[kn & 1][mt][3] = packh2(w.z, w.w);
                }
            }
            uint32_t (*cu)[4] = afb[kt & 1];
            #pragma unroll
            for (int np = 0; np < 4; np++) {
                uint4 B = w1f[(kt * 8 + nbase + np) * 32 + lane];
                mma16816(acc[0][2*np],   cu[0][0], cu[0][1], cu[0][2], cu[0][3], B.x, B.y);
                mma16816(acc[0][2*np+1], cu[0][0], cu[0][1], cu[0][2], cu[0][3], B.z, B.w);
                mma16816(acc[1][2*np],   cu[1][0], cu[1][1], cu[1][2], cu[1][3], B.x, B.y);
                mma16816(acc[1][2*np+1], cu[1][0], cu[1][1], cu[1][2], cu[1][3], B.z, B.w);
            }
        }

        // ---- epilogue 1: +b1, partial LN moments over own 64 cols ----
        float s[2][2] = {{0.f, 0.f}, {0.f, 0.f}};
        float ss[2][2] = {{0.f, 0.f}, {0.f, 0.f}};
        #pragma unroll
        for (int mt = 0; mt < 2; mt++) {
            #pragma unroll
            for (int np = 0; np < 4; np++) {
                float4 bb = *reinterpret_cast<const float4*>(b1s + 16 * (nbase + np) + 4 * c4);
                float* e0 = acc[mt][2*np];
                float* e1 = acc[mt][2*np+1];
                e0[0] += bb.x; e0[1] += bb.y; e0[2] += bb.x; e0[3] += bb.y;
                e1[0] += bb.z; e1[1] += bb.w; e1[2] += bb.z; e1[3] += bb.w;
                s[mt][0] += e0[0] + e0[1] + e1[0] + e1[1];
                s[mt][1] += e0[2] + e0[3] + e1[2] + e1[3];
                ss[mt][0] = fmaf(e0[0], e0[0], ss[mt][0]);
                ss[mt][0] = fmaf(e0[1], e0[1], ss[mt][0]);
                ss[mt][0] = fmaf(e1[0], e1[0], ss[mt][0]);
                ss[mt][0] = fmaf(e1[1], e1[1], ss[mt][0]);
                ss[mt][1] = fmaf(e0[2], e0[2], ss[mt][1]);
                ss[mt][1] = fmaf(e0[3], e0[3], ss[mt][1]);
                ss[mt][1] = fmaf(e1[2], e1[2], ss[mt][1]);
                ss[mt][1] = fmaf(e1[3], e1[3], ss[mt][1]);
            }
            #pragma unroll
            for (int rh = 0; rh < 2; rh++) {
                s[mt][rh]  += __shfl_xor_sync(0xffffffffu, s[mt][rh], 1);
                s[mt][rh]  += __shfl_xor_sync(0xffffffffu, s[mt][rh], 2);
                ss[mt][rh] += __shfl_xor_sync(0xffffffffu, ss[mt][rh], 1);
                ss[mt][rh] += __shfl_xor_sync(0xffffffffu, ss[mt][rh], 2);
            }
        }
        if (c4 == 0) {
            #pragma unroll
            for (int mt = 0; mt < 2; mt++) {
                psm[(pair * 2 + role) * 32 + mt * 16 + q]     = make_float2(s[mt][0], ss[mt][0]);
                psm[(pair * 2 + role) * 32 + mt * 16 + q + 8] = make_float2(s[mt][1], ss[mt][1]);
            }
        }
        __syncthreads();   // S1: psums visible to partner

        float mu[2][2], rs[2][2];
        #pragma unroll
        for (int mt = 0; mt < 2; mt++)
            #pragma unroll
            for (int rh = 0; rh < 2; rh++) {
                float2 pp = psm[(pair * 2 + (1 ^ role)) * 32 + mt * 16 + q + rh * 8];
                float st = s[mt][rh] + pp.x;
                float sq = ss[mt][rh] + pp.y;
                float m = st * (1.f / 128.f);
                mu[mt][rh] = m;
                rs[mt][rh] = rsqrtf(fmaf(-m, m, sq * (1.f / 128.f)) + LN_EPS);
            }

        // LN + silu -> a2f fragments (own kt2 tiles = nbase..nbase+3)
        uint32_t a2f[2][4][4];
        #pragma unroll
        for (int mt = 0; mt < 2; mt++)
            #pragma unroll
            for (int j = 0; j < 4; j++) {
                float4 gg  = *reinterpret_cast<const float4*>(gms + 16 * (nbase + j) + 4 * c4);
                float4 bt4 = *reinterpret_cast<const float4*>(bts + 16 * (nbase + j) + 4 * c4);
                float* e0 = acc[mt][2*j];
                float* e1 = acc[mt][2*j+1];
                float y00 = silu((e0[0] - mu[mt][0]) * rs[mt][0] * gg.x + bt4.x);
                float y01 = silu((e0[1] - mu[mt][0]) * rs[mt][0] * gg.y + bt4.y);
                float y10 = silu((e0[2] - mu[mt][1]) * rs[mt][1] * gg.x + bt4.x);
                float y11 = silu((e0[3] - mu[mt][1]) * rs[mt][1] * gg.y + bt4.y);
                float z00 = silu((e1[0] - mu[mt][0]) * rs[mt][0] * gg.z + bt4.z);
                float z01 = silu((e1[1] - mu[mt][0]) * rs[mt][0] * gg.w + bt4.w);
                float z10 = silu((e1[2] - mu[mt][1]) * rs[mt][1] * gg.z + bt4.z);
                float z11 = silu((e1[3] - mu[mt][1]) * rs[mt][1] * gg.w + bt4.w);
                a2f[mt][j][0] = packh2(y00, y01);
                a2f[mt][j][1] = packh2(y10, y11);
                a2f[mt][j][2] = packh2(z00, z01);
                a2f[mt][j][3] = packh2(z10, z11);
            }

        // ---- GEMM2 in two M=16 phases with activation exchange ----
        #pragma unroll
        for (int mt = 0; mt < 2; mt++) {
            #pragma unroll
            for (int j = 0; j < 4; j++)
                a2x[(pair * 8 + nbase + j) * 32 + lane] =
                    make_uint4(a2f[mt][j][0], a2f[mt][j][1], a2f[mt][j][2], a2f[mt][j][3]);
            __syncthreads();   // S2/S4: full activation fragment set ready

            float c2[8][4];
            #pragma unroll
            for (int nt = 0; nt < 8; nt++) {
                c2[nt][0] = 0.f; c2[nt][1] = 0.f; c2[nt][2] = 0.f; c2[nt][3] = 0.f;
            }
            #pragma unroll
            for (int kg = 0; kg < 8; kg++) {
                uint4 A = a2x[(pair * 8 + kg) * 32 + lane];
                #pragma unroll
                for (int np = 0; np < 4; np++) {
                    uint4 B = w2f[(kg * 8 + nbase + np) * 32 + lane];
                    mma16816(c2[2*np],   A.x, A.y, A.z, A.w, B.x, B.y);
                    mma16816(c2[2*np+1], A.x, A.y, A.z, A.w, B.z, B.w);
                }
            }

            // epilogue 2: +b2, silu, float4 stores (rows of this mtile)
            const int rm0 = rbase + mt * 16 + q;
            const int rm1 = rm0 + 8;
            const bool v0 = rm0 < E;
            const bool v1 = rm1 < E;
            #pragma unroll
            for (int np = 0; np < 4; np++) {
                float4 bb = *reinterpret_cast<const float4*>(b2s + 16 * (nbase + np) + 4 * c4);
                float4 o0, o1;
                o0.x = silu(c2[2*np][0]   + bb.x);
                o0.y = silu(c2[2*np][1]   + bb.y);
                o0.z = silu(c2[2*np+1][0] + bb.z);
                o0.w = silu(c2[2*np+1][1] + bb.w);
                o1.x = silu(c2[2*np][2]   + bb.x);
                o1.y = silu(c2[2*np][3]   + bb.y);
                o1.z = silu(c2[2*np+1][2] + bb.z);
                o1.w = silu(c2[2*np+1][3] + bb.w);
                const int col = 16 * (nbase + np) + 4 * c4;
                if (v0) *reinterpret_cast<float4*>(out + (size_t)rm0 * 128 + col) = o0;
                if (v1) *reinterpret_cast<float4*>(out + (size_t)rm1 * 128 + col) = o1;
            }
            __syncthreads();   // S3/S5: a2x reads done before next overwrite
        }
    }
}

// ===================== launch =====================
extern "C" void kernel_launch(void* const* d_in, const int* in_sizes, int n_in,
                              void* d_out, int out_size)
{
    (void)n_in; (void)out_size;
    const float* src = (const float*)d_in[0];
    const float* edg = (const float*)d_in[1];
    const float* W1  = (const float*)d_in[2];
    const float* b1  = (const float*)d_in[3];
    const float* gma = (const float*)d_in[4];
    const float* bta = (const float*)d_in[5];
    const float* W2  = (const float*)d_in[6];
    const float* b2  = (const float*)d_in[7];
    float* out = (float*)d_out;

    const int E = in_sizes[0] / 128;
    const int n_big = (E + 31) / 32;
    const int grid = 304;
    const int n_pairs = grid * 4;
    const int n_iter = (n_big + n_pairs - 1) / n_pairs;

    cudaFuncSetAttribute(edge_mlp_kernel,
                         cudaFuncAttributeMaxDynamicSharedMemorySize, SMEM_BYTES);
    edge_mlp_kernel<<<grid, 256, SMEM_BYTES>>>(src, edg, W1, b1, gma, bta, W2, b2,
                                               out, E, n_iter);
}

// round 11
// speedup vs baseline: 1.7652x; 1.7652x over previous
#include <cuda_runtime.h>
#include <cuda_fp16.h>
#include <cstdint>

// ============================================================================
// EdgeMLP: out = silu( silu(LN(concat(src,edge) @ W1 + b1)) @ W2 + b2 )
// E rows; in 192 (128 src + 64 edge), hid/out 128.
//
// R11 = R8 verbatim + epilogue params moved from smem to __constant__.
// R10 post-mortem: M32/N64 tiling is a wavefront WASH (B1 halving exactly
// cancelled by A duplication/exchange) -> R8 structure is the optimum.
// R8 profile: L1 86.7% binder. Param float4 reads = 32 LDS.128 = 128 wf/group
// = 13% of l1tex traffic; __constant__ reads use the separate const-cache
// port (4-way replay from c4 divergence, benign). Filled via D2D
// cudaMemcpyToSymbolAsync (graph-capturable, no allocation).
//   - keeps: K/N-permuted fragments (24 LDG.128 / 16 STG.128 per group),
//     one-pass LN moments, tanh.approx silu, fragment-order weights in smem,
//     warp-independent 16-row groups, no syncs in main loop, 256thr x 2 CTA/SM
// ============================================================================

static constexpr int NT1 = 16;   // 16 n8-tiles  -> N=128
static constexpr int NP1 = 8;    // 8 n16 pairs
static constexpr int KT1 = 12;   // 12 k16-tiles -> K=192
static constexpr int KT2 = 8;    // K=128
static constexpr float LN_EPS = 1e-5f;

// constant-memory parameters: [0:128)=b1, [128:256)=gamma, [256:384)=beta,
// [384:512)=b2
__constant__ float cPAR[512];

// dynamic smem layout (bytes) — weights only now
static constexpr int SM_W1F = 0;                              // 12*8*32 uint4 = 49152
static constexpr int SM_W2F = SM_W1F + KT1 * NP1 * 32 * 16;   // 49152
static constexpr int SMEM_BYTES = SM_W2F + KT2 * NP1 * 32 * 16;  // 81920

__device__ __forceinline__ uint32_t packh2(float a, float b) {
    __half2 h = __floats2half2_rn(a, b);
    return *reinterpret_cast<uint32_t*>(&h);
}

__device__ __forceinline__ void mma16816(float c[4],
                                         uint32_t a0, uint32_t a1, uint32_t a2, uint32_t a3,
                                         uint32_t b0, uint32_t b1) {
    asm volatile(
        "mma.sync.aligned.m16n8k16.row.col.f32.f16.f16.f32 "
        "{%0,%1,%2,%3}, {%4,%5,%6,%7}, {%8,%9}, {%0,%1,%2,%3};"
        : "+f"(c[0]), "+f"(c[1]), "+f"(c[2]), "+f"(c[3])
        : "r"(a0), "r"(a1), "r"(a2), "r"(a3), "r"(b0), "r"(b1));
}

// silu(x) = x * sigmoid(x) = 0.5x * (1 + tanh(x/2)) : 1 MUFU + 2 FMA-class ops
__device__ __forceinline__ float silu(float x) {
    float hx = 0.5f * x;
    float t;
    asm("tanh.approx.f32 %0, %1;" : "=f"(t) : "f"(hx));
    return fmaf(hx, t, hx);
}

__global__ void __launch_bounds__(256, 2) edge_mlp_kernel(
    const float* __restrict__ src, const float* __restrict__ edg,
    const float* __restrict__ W1, const float* __restrict__ W2,
    float* __restrict__ out, int E, int n_groups)
{
    extern __shared__ char smem[];
    uint4* w1f = reinterpret_cast<uint4*>(smem + SM_W1F);
    uint4* w2f = reinterpret_cast<uint4*>(smem + SM_W2F);

    const int tid  = threadIdx.x;
    const int lane = tid & 31;
    const int wid  = tid >> 5;
    const int q    = lane >> 2;   // 0..7  (row within m16: q and q+8; also B n-pos)
    const int c4   = lane & 3;    // 0..3

    // ---- one-time: fragment-order weight swizzle into smem (as R8) ----
    for (int e = tid; e < KT1 * NP1 * 32; e += 256) {
        int l = e & 31, slot = e >> 5;
        int np = slot & 7, kt = slot >> 3;
        int k = kt * 16 + 4 * (l & 3);
        int qq = l >> 2;
        int n0 = np * 16 + 4 * (qq >> 1) + (qq & 1);
        int n1 = n0 + 2;
        uint4 v;
        v.x = packh2(W1[k * 128 + n0], W1[(k + 1) * 128 + n0]);
        v.y = packh2(W1[(k + 2) * 128 + n0], W1[(k + 3) * 128 + n0]);
        v.z = packh2(W1[k * 128 + n1], W1[(k + 1) * 128 + n1]);
        v.w = packh2(W1[(k + 2) * 128 + n1], W1[(k + 3) * 128 + n1]);
        w1f[e] = v;
    }
    for (int e = tid; e < KT2 * NP1 * 32; e += 256) {
        int l = e & 31, slot = e >> 5;
        int np = slot & 7, kt = slot >> 3;
        int k = kt * 16 + 4 * (l & 3);
        int qq = l >> 2;
        int n0 = np * 16 + 4 * (qq >> 1) + (qq & 1);
        int n1 = n0 + 2;
        uint4 v;
        v.x = packh2(W2[k * 128 + n0], W2[(k + 1) * 128 + n0]);
        v.y = packh2(W2[(k + 2) * 128 + n0], W2[(k + 3) * 128 + n0]);
        v.z = packh2(W2[k * 128 + n1], W2[(k + 1) * 128 + n1]);
        v.w = packh2(W2[(k + 2) * 128 + n1], W2[(k + 3) * 128 + n1]);
        w2f[e] = v;
    }
    __syncthreads();

    // ---- persistent loop: each warp processes independent 16-row groups ----
    const int warp_global = blockIdx.x * 8 + wid;
    const int warp_step   = gridDim.x * 8;

    for (int g = warp_global; g < n_groups; g += warp_step) {
        const int row0 = g * 16 + q;
        const int row1 = row0 + 8;
        const size_t r0 = (size_t)min(row0, E - 1);
        const size_t r1 = (size_t)min(row1, E - 1);

        // ---- load A (K-permuted, float4) ----
        uint32_t af[KT1][4];
        #pragma unroll
        for (int kt = 0; kt < 8; kt++) {
            float4 v = *reinterpret_cast<const float4*>(src + r0 * 128 + kt * 16 + 4 * c4);
            float4 w = *reinterpret_cast<const float4*>(src + r1 * 128 + kt * 16 + 4 * c4);
            af[kt][0] = packh2(v.x, v.y);   // a0: frag k-pos 2c4,2c4+1 = phys +0,+1
            af[kt][2] = packh2(v.z, v.w);   // a2: frag k-pos +8,+9     = phys +2,+3
            af[kt][1] = packh2(w.x, w.y);   // a1: rows +8
            af[kt][3] = packh2(w.z, w.w);   // a3
        }
        #pragma unroll
        for (int kt = 8; kt < 12; kt++) {
            float4 v = *reinterpret_cast<const float4*>(edg + r0 * 64 + (kt - 8) * 16 + 4 * c4);
            float4 w = *reinterpret_cast<const float4*>(edg + r1 * 64 + (kt - 8) * 16 + 4 * c4);
            af[kt][0] = packh2(v.x, v.y);
            af[kt][2] = packh2(v.z, v.w);
            af[kt][1] = packh2(w.x, w.y);
            af[kt][3] = packh2(w.z, w.w);
        }

        // ================= GEMM1: [16x192] @ W1 -> acc[16 nt][4] =================
        float acc[NT1][4];
        #pragma unroll
        for (int nt = 0; nt < NT1; nt++) {
            acc[nt][0] = 0.f; acc[nt][1] = 0.f; acc[nt][2] = 0.f; acc[nt][3] = 0.f;
        }
        #pragma unroll
        for (int kt = 0; kt < KT1; kt++) {
            const uint4* wrow = w1f + (kt * NP1) * 32 + lane;
            #pragma unroll
            for (int np = 0; np < NP1; np++) {
                uint4 B = wrow[np * 32];
                mma16816(acc[2 * np],     af[kt][0], af[kt][1], af[kt][2], af[kt][3], B.x, B.y);
                mma16816(acc[2 * np + 1], af[kt][0], af[kt][1], af[kt][2], af[kt][3], B.z, B.w);
            }
        }

        // ===== epilogue 1: +b1, one-pass LN moments (sum & sumsq), SiLU =====
        float s0 = 0.f, s1 = 0.f, ss0 = 0.f, ss1 = 0.f;
        #pragma unroll
        for (int np = 0; np < NP1; np++) {
            float4 bb = *reinterpret_cast<const float4*>(cPAR + 16 * np + 4 * c4);
            acc[2*np][0]   += bb.x; acc[2*np][1]   += bb.y;
            acc[2*np][2]   += bb.x; acc[2*np][3]   += bb.y;
            acc[2*np+1][0] += bb.z; acc[2*np+1][1] += bb.w;
            acc[2*np+1][2] += bb.z; acc[2*np+1][3] += bb.w;
            s0 += acc[2*np][0] + acc[2*np][1] + acc[2*np+1][0] + acc[2*np+1][1];
            s1 += acc[2*np][2] + acc[2*np][3] + acc[2*np+1][2] + acc[2*np+1][3];
            ss0 = fmaf(acc[2*np][0],   acc[2*np][0],   ss0);
            ss0 = fmaf(acc[2*np][1],   acc[2*np][1],   ss0);
            ss0 = fmaf(acc[2*np+1][0], acc[2*np+1][0], ss0);
            ss0 = fmaf(acc[2*np+1][1], acc[2*np+1][1], ss0);
            ss1 = fmaf(acc[2*np][2],   acc[2*np][2],   ss1);
            ss1 = fmaf(acc[2*np][3],   acc[2*np][3],   ss1);
            ss1 = fmaf(acc[2*np+1][2], acc[2*np+1][2], ss1);
            ss1 = fmaf(acc[2*np+1][3], acc[2*np+1][3], ss1);
        }
        s0  += __shfl_xor_sync(0xffffffffu, s0, 1);
        s0  += __shfl_xor_sync(0xffffffffu, s0, 2);
        s1  += __shfl_xor_sync(0xffffffffu, s1, 1);
        s1  += __shfl_xor_sync(0xffffffffu, s1, 2);
        ss0 += __shfl_xor_sync(0xffffffffu, ss0, 1);
        ss0 += __shfl_xor_sync(0xffffffffu, ss0, 2);
        ss1 += __shfl_xor_sync(0xffffffffu, ss1, 1);
        ss1 += __shfl_xor_sync(0xffffffffu, ss1, 2);
        const float mu0 = s0 * (1.f / 128.f);
        const float mu1 = s1 * (1.f / 128.f);
        const float rs0 = rsqrtf(fmaf(-mu0, mu0, ss0 * (1.f / 128.f)) + LN_EPS);
        const float rs1 = rsqrtf(fmaf(-mu1, mu1, ss1 * (1.f / 128.f)) + LN_EPS);

        // C (N-permuted) -> A fragment of GEMM2 (K-permuted identically): free.
        uint32_t a2f[KT2][4];
        #pragma unroll
        for (int np = 0; np < NP1; np++) {
            float4 gg  = *reinterpret_cast<const float4*>(cPAR + 128 + 16 * np + 4 * c4);
            float4 bt4 = *reinterpret_cast<const float4*>(cPAR + 256 + 16 * np + 4 * c4);
            float y00 = silu((acc[2*np][0]   - mu0) * rs0 * gg.x + bt4.x);
            float y01 = silu((acc[2*np][1]   - mu0) * rs0 * gg.y + bt4.y);
            float y10 = silu((acc[2*np][2]   - mu1) * rs1 * gg.x + bt4.x);
            float y11 = silu((acc[2*np][3]   - mu1) * rs1 * gg.y + bt4.y);
            float z00 = silu((acc[2*np+1][0] - mu0) * rs0 * gg.z + bt4.z);
            float z01 = silu((acc[2*np+1][1] - mu0) * rs0 * gg.w + bt4.w);
            float z10 = silu((acc[2*np+1][2] - mu1) * rs1 * gg.z + bt4.z);
            float z11 = silu((acc[2*np+1][3] - mu1) * rs1 * gg.w + bt4.w);
            a2f[np][0] = packh2(y00, y01);  // a0
            a2f[np][1] = packh2(y10, y11);  // a1 (rows +8)
            a2f[np][2] = packh2(z00, z01);  // a2
            a2f[np][3] = packh2(z10, z11);  // a3
        }

        // ================= GEMM2: [16x128] @ W2 -> acc (reused) =================
        #pragma unroll
        for (int nt = 0; nt < NT1; nt++) {
            acc[nt][0] = 0.f; acc[nt][1] = 0.f; acc[nt][2] = 0.f; acc[nt][3] = 0.f;
        }
        #pragma unroll
        for (int kt = 0; kt < KT2; kt++) {
            const uint4* wrow = w2f + (kt * NP1) * 32 + lane;
            #pragma unroll
            for (int np = 0; np < NP1; np++) {
                uint4 B = wrow[np * 32];
                mma16816(acc[2 * np],     a2f[kt][0], a2f[kt][1], a2f[kt][2], a2f[kt][3], B.x, B.y);
                mma16816(acc[2 * np + 1], a2f[kt][0], a2f[kt][1], a2f[kt][2], a2f[kt][3], B.z, B.w);
            }
        }

        // ================= epilogue 2: +b2, SiLU, store (float4) =================
        const bool val0 = (row0 < E);
        const bool val1 = (row1 < E);
        #pragma unroll
        for (int np = 0; np < NP1; np++) {
            float4 bb = *reinterpret_cast<const float4*>(cPAR + 384 + 16 * np + 4 * c4);
            float4 o0, o1;
            o0.x = silu(acc[2*np][0]   + bb.x);
            o0.y = silu(acc[2*np][1]   + bb.y);
            o0.z = silu(acc[2*np+1][0] + bb.z);
            o0.w = silu(acc[2*np+1][1] + bb.w);
            o1.x = silu(acc[2*np][2]   + bb.x);
            o1.y = silu(acc[2*np][3]   + bb.y);
            o1.z = silu(acc[2*np+1][2] + bb.z);
            o1.w = silu(acc[2*np+1][3] + bb.w);
            const int col = 16 * np + 4 * c4;
            if (val0) *reinterpret_cast<float4*>(out + (size_t)row0 * 128 + col) = o0;
            if (val1) *reinterpret_cast<float4*>(out + (size_t)row1 * 128 + col) = o1;
        }
    }
}

// ===================== launch =====================
extern "C" void kernel_launch(void* const* d_in, const int* in_sizes, int n_in,
                              void* d_out, int out_size)
{
    (void)n_in; (void)out_size;
    const float* src = (const float*)d_in[0];
    const float* edg = (const float*)d_in[1];
    const float* W1  = (const float*)d_in[2];
    const float* b1  = (const float*)d_in[3];
    const float* gma = (const float*)d_in[4];
    const float* bta = (const float*)d_in[5];
    const float* W2  = (const float*)d_in[6];
    const float* b2  = (const float*)d_in[7];
    float* out = (float*)d_out;

    const int E = in_sizes[0] / 128;
    const int n_groups = (E + 15) / 16;

    // params -> __constant__ (device-to-device, graph-capturable, no alloc)
    cudaMemcpyToSymbolAsync(cPAR, b1,  128 * sizeof(float), 0,
                            cudaMemcpyDeviceToDevice, 0);
    cudaMemcpyToSymbolAsync(cPAR, gma, 128 * sizeof(float), 128 * sizeof(float),
                            cudaMemcpyDeviceToDevice, 0);
    cudaMemcpyToSymbolAsync(cPAR, bta, 128 * sizeof(float), 256 * sizeof(float),
                            cudaMemcpyDeviceToDevice, 0);
    cudaMemcpyToSymbolAsync(cPAR, b2,  128 * sizeof(float), 384 * sizeof(float),
                            cudaMemcpyDeviceToDevice, 0);

    cudaFuncSetAttribute(edge_mlp_kernel,
                         cudaFuncAttributeMaxDynamicSharedMemorySize, SMEM_BYTES);
    edge_mlp_kernel<<<304, 256, SMEM_BYTES>>>(src, edg, W1, W2, out, E, n_groups);
}

// round 12
// speedup vs baseline: 1.8302x; 1.0368x over previous
#include <cuda_runtime.h>
#include <cuda_fp16.h>
#include <cstdint>

// ============================================================================
// EdgeMLP: out = silu( silu(LN(concat(src,edge) @ W1 + b1)) @ W2 + b2 )
// E rows; in 192 (128 src + 64 edge), hid/out 128.
//
// R12 = R11 kernel minus the 4 graph memcpy nodes (R11: kernel 156.9 but wall
// 163.9 = kernel + ~7us of cudaMemcpyToSymbolAsync node overhead).
//   - epilogue params read via __ldg float4 straight from gmem: c4-divergent
//     LDG.128 spans 64B = ~2 wf (cheaper than R8's 4-way LDS replay), L1-hot
//   - zero-register prefetch.global.L2 of next group's A rows before GEMM2
//     (R6 lesson: register prefetch across GEMM2 spills; L2 prefetch is free)
//   - unchanged: K/N-permuted fragments (24 LDG.128 / 16 STG.128 per group),
//     one-pass LN moments, tanh.approx silu, fragment-order weights in smem,
//     warp-independent 16-row groups, 256thr x 2 CTA/SM, no main-loop syncs
// ============================================================================

static constexpr int NT1 = 16;   // 16 n8-tiles  -> N=128
static constexpr int NP1 = 8;    // 8 n16 pairs
static constexpr int KT1 = 12;   // 12 k16-tiles -> K=192
static constexpr int KT2 = 8;    // K=128
static constexpr float LN_EPS = 1e-5f;

// dynamic smem layout (bytes) — weights only
static constexpr int SM_W1F = 0;                              // 12*8*32 uint4 = 49152
static constexpr int SM_W2F = SM_W1F + KT1 * NP1 * 32 * 16;   // 49152
static constexpr int SMEM_BYTES = SM_W2F + KT2 * NP1 * 32 * 16;  // 81920

__device__ __forceinline__ uint32_t packh2(float a, float b) {
    __half2 h = __floats2half2_rn(a, b);
    return *reinterpret_cast<uint32_t*>(&h);
}

__device__ __forceinline__ void mma16816(float c[4],
                                         uint32_t a0, uint32_t a1, uint32_t a2, uint32_t a3,
                                         uint32_t b0, uint32_t b1) {
    asm volatile(
        "mma.sync.aligned.m16n8k16.row.col.f32.f16.f16.f32 "
        "{%0,%1,%2,%3}, {%4,%5,%6,%7}, {%8,%9}, {%0,%1,%2,%3};"
        : "+f"(c[0]), "+f"(c[1]), "+f"(c[2]), "+f"(c[3])
        : "r"(a0), "r"(a1), "r"(a2), "r"(a3), "r"(b0), "r"(b1));
}

// silu(x) = x * sigmoid(x) = 0.5x * (1 + tanh(x/2)) : 1 MUFU + 2 FMA-class ops
__device__ __forceinline__ float silu(float x) {
    float hx = 0.5f * x;
    float t;
    asm("tanh.approx.f32 %0, %1;" : "=f"(t) : "f"(hx));
    return fmaf(hx, t, hx);
}

__device__ __forceinline__ void prefetch_l2(const void* p) {
    asm volatile("prefetch.global.L2 [%0];" :: "l"(p));
}

__global__ void __launch_bounds__(256, 2) edge_mlp_kernel(
    const float* __restrict__ src, const float* __restrict__ edg,
    const float* __restrict__ W1, const float* __restrict__ b1,
    const float* __restrict__ gma, const float* __restrict__ bta,
    const float* __restrict__ W2, const float* __restrict__ b2,
    float* __restrict__ out, int E, int n_groups)
{
    extern __shared__ char smem[];
    uint4* w1f = reinterpret_cast<uint4*>(smem + SM_W1F);
    uint4* w2f = reinterpret_cast<uint4*>(smem + SM_W2F);

    const int tid  = threadIdx.x;
    const int lane = tid & 31;
    const int wid  = tid >> 5;
    const int q    = lane >> 2;   // 0..7  (row within m16: q and q+8; also B n-pos)
    const int c4   = lane & 3;    // 0..3

    // ---- one-time: fragment-order weight swizzle into smem (as R8) ----
    for (int e = tid; e < KT1 * NP1 * 32; e += 256) {
        int l = e & 31, slot = e >> 5;
        int np = slot & 7, kt = slot >> 3;
        int k = kt * 16 + 4 * (l & 3);
        int qq = l >> 2;
        int n0 = np * 16 + 4 * (qq >> 1) + (qq & 1);
        int n1 = n0 + 2;
        uint4 v;
        v.x = packh2(W1[k * 128 + n0], W1[(k + 1) * 128 + n0]);
        v.y = packh2(W1[(k + 2) * 128 + n0], W1[(k + 3) * 128 + n0]);
        v.z = packh2(W1[k * 128 + n1], W1[(k + 1) * 128 + n1]);
        v.w = packh2(W1[(k + 2) * 128 + n1], W1[(k + 3) * 128 + n1]);
        w1f[e] = v;
    }
    for (int e = tid; e < KT2 * NP1 * 32; e += 256) {
        int l = e & 31, slot = e >> 5;
        int np = slot & 7, kt = slot >> 3;
        int k = kt * 16 + 4 * (l & 3);
        int qq = l >> 2;
        int n0 = np * 16 + 4 * (qq >> 1) + (qq & 1);
        int n1 = n0 + 2;
        uint4 v;
        v.x = packh2(W2[k * 128 + n0], W2[(k + 1) * 128 + n0]);
        v.y = packh2(W2[(k + 2) * 128 + n0], W2[(k + 3) * 128 + n0]);
        v.z = packh2(W2[k * 128 + n1], W2[(k + 1) * 128 + n1]);
        v.w = packh2(W2[(k + 2) * 128 + n1], W2[(k + 3) * 128 + n1]);
        w2f[e] = v;
    }
    __syncthreads();

    // ---- persistent loop: each warp processes independent 16-row groups ----
    const int warp_global = blockIdx.x * 8 + wid;
    const int warp_step   = gridDim.x * 8;

    for (int g = warp_global; g < n_groups; g += warp_step) {
        const int row0 = g * 16 + q;
        const int row1 = row0 + 8;
        const size_t r0 = (size_t)min(row0, E - 1);
        const size_t r1 = (size_t)min(row1, E - 1);

        // ---- load A (K-permuted, float4) ----
        uint32_t af[KT1][4];
        #pragma unroll
        for (int kt = 0; kt < 8; kt++) {
            float4 v = *reinterpret_cast<const float4*>(src + r0 * 128 + kt * 16 + 4 * c4);
            float4 w = *reinterpret_cast<const float4*>(src + r1 * 128 + kt * 16 + 4 * c4);
            af[kt][0] = packh2(v.x, v.y);   // a0: frag k-pos 2c4,2c4+1 = phys +0,+1
            af[kt][2] = packh2(v.z, v.w);   // a2: frag k-pos +8,+9     = phys +2,+3
            af[kt][1] = packh2(w.x, w.y);   // a1: rows +8
            af[kt][3] = packh2(w.z, w.w);   // a3
        }
        #pragma unroll
        for (int kt = 8; kt < 12; kt++) {
            float4 v = *reinterpret_cast<const float4*>(edg + r0 * 64 + (kt - 8) * 16 + 4 * c4);
            float4 w = *reinterpret_cast<const float4*>(edg + r1 * 64 + (kt - 8) * 16 + 4 * c4);
            af[kt][0] = packh2(v.x, v.y);
            af[kt][2] = packh2(v.z, v.w);
            af[kt][1] = packh2(w.x, w.y);
            af[kt][3] = packh2(w.z, w.w);
        }

        // ================= GEMM1: [16x192] @ W1 -> acc[16 nt][4] =================
        float acc[NT1][4];
        #pragma unroll
        for (int nt = 0; nt < NT1; nt++) {
            acc[nt][0] = 0.f; acc[nt][1] = 0.f; acc[nt][2] = 0.f; acc[nt][3] = 0.f;
        }
        #pragma unroll
        for (int kt = 0; kt < KT1; kt++) {
            const uint4* wrow = w1f + (kt * NP1) * 32 + lane;
            #pragma unroll
            for (int np = 0; np < NP1; np++) {
                uint4 B = wrow[np * 32];
                mma16816(acc[2 * np],     af[kt][0], af[kt][1], af[kt][2], af[kt][3], B.x, B.y);
                mma16816(acc[2 * np + 1], af[kt][0], af[kt][1], af[kt][2], af[kt][3], B.z, B.w);
            }
        }

        // ===== epilogue 1: +b1, one-pass LN moments (sum & sumsq), SiLU =====
        float s0 = 0.f, s1 = 0.f, ss0 = 0.f, ss1 = 0.f;
        #pragma unroll
        for (int np = 0; np < NP1; np++) {
            float4 bb = __ldg(reinterpret_cast<const float4*>(b1 + 16 * np + 4 * c4));
            acc[2*np][0]   += bb.x; acc[2*np][1]   += bb.y;
            acc[2*np][2]   += bb.x; acc[2*np][3]   += bb.y;
            acc[2*np+1][0] += bb.z; acc[2*np+1][1] += bb.w;
            acc[2*np+1][2] += bb.z; acc[2*np+1][3] += bb.w;
            s0 += acc[2*np][0] + acc[2*np][1] + acc[2*np+1][0] + acc[2*np+1][1];
            s1 += acc[2*np][2] + acc[2*np][3] + acc[2*np+1][2] + acc[2*np+1][3];
            ss0 = fmaf(acc[2*np][0],   acc[2*np][0],   ss0);
            ss0 = fmaf(acc[2*np][1],   acc[2*np][1],   ss0);
            ss0 = fmaf(acc[2*np+1][0], acc[2*np+1][0], ss0);
            ss0 = fmaf(acc[2*np+1][1], acc[2*np+1][1], ss0);
            ss1 = fmaf(acc[2*np][2],   acc[2*np][2],   ss1);
            ss1 = fmaf(acc[2*np][3],   acc[2*np][3],   ss1);
            ss1 = fmaf(acc[2*np+1][2], acc[2*np+1][2], ss1);
            ss1 = fmaf(acc[2*np+1][3], acc[2*np+1][3], ss1);
        }
        s0  += __shfl_xor_sync(0xffffffffu, s0, 1);
        s0  += __shfl_xor_sync(0xffffffffu, s0, 2);
        s1  += __shfl_xor_sync(0xffffffffu, s1, 1);
        s1  += __shfl_xor_sync(0xffffffffu, s1, 2);
        ss0 += __shfl_xor_sync(0xffffffffu, ss0, 1);
        ss0 += __shfl_xor_sync(0xffffffffu, ss0, 2);
        ss1 += __shfl_xor_sync(0xffffffffu, ss1, 1);
        ss1 += __shfl_xor_sync(0xffffffffu, ss1, 2);
        const float mu0 = s0 * (1.f / 128.f);
        const float mu1 = s1 * (1.f / 128.f);
        const float rs0 = rsqrtf(fmaf(-mu0, mu0, ss0 * (1.f / 128.f)) + LN_EPS);
        const float rs1 = rsqrtf(fmaf(-mu1, mu1, ss1 * (1.f / 128.f)) + LN_EPS);

        // C (N-permuted) -> A fragment of GEMM2 (K-permuted identically): free.
        uint32_t a2f[KT2][4];
        #pragma unroll
        for (int np = 0; np < NP1; np++) {
            float4 gg  = __ldg(reinterpret_cast<const float4*>(gma + 16 * np + 4 * c4));
            float4 bt4 = __ldg(reinterpret_cast<const float4*>(bta + 16 * np + 4 * c4));
            float y00 = silu((acc[2*np][0]   - mu0) * rs0 * gg.x + bt4.x);
            float y01 = silu((acc[2*np][1]   - mu0) * rs0 * gg.y + bt4.y);
            float y10 = silu((acc[2*np][2]   - mu1) * rs1 * gg.x + bt4.x);
            float y11 = silu((acc[2*np][3]   - mu1) * rs1 * gg.y + bt4.y);
            float z00 = silu((acc[2*np+1][0] - mu0) * rs0 * gg.z + bt4.z);
            float z01 = silu((acc[2*np+1][1] - mu0) * rs0 * gg.w + bt4.w);
            float z10 = silu((acc[2*np+1][2] - mu1) * rs1 * gg.z + bt4.z);
            float z11 = silu((acc[2*np+1][3] - mu1) * rs1 * gg.w + bt4.w);
            a2f[np][0] = packh2(y00, y01);  // a0
            a2f[np][1] = packh2(y10, y11);  // a1 (rows +8)
            a2f[np][2] = packh2(z00, z01);  // a2
            a2f[np][3] = packh2(z10, z11);  // a3
        }

        // ---- zero-register L2 prefetch of next group's A rows ----
        {
            int gn = g + warp_step;
            if (gn > n_groups - 1) gn = n_groups - 1;
            size_t p0 = (size_t)min(gn * 16 + q,     E - 1);
            size_t p1 = (size_t)min(gn * 16 + q + 8, E - 1);
            prefetch_l2(src + p0 * 128 + c4 * 32);        // 4 lanes cover 512B row
            prefetch_l2(src + p1 * 128 + c4 * 32);
            prefetch_l2(edg + p0 * 64 + (c4 & 1) * 32);   // 2 lines per 256B row
            prefetch_l2(edg + p1 * 64 + (c4 & 1) * 32);
        }

        // ================= GEMM2: [16x128] @ W2 -> acc (reused) =================
        #pragma unroll
        for (int nt = 0; nt < NT1; nt++) {
            acc[nt][0] = 0.f; acc[nt][1] = 0.f; acc[nt][2] = 0.f; acc[nt][3] = 0.f;
        }
        #pragma unroll
        for (int kt = 0; kt < KT2; kt++) {
            const uint4* wrow = w2f + (kt * NP1) * 32 + lane;
            #pragma unroll
            for (int np = 0; np < NP1; np++) {
                uint4 B = wrow[np * 32];
                mma16816(acc[2 * np],     a2f[kt][0], a2f[kt][1], a2f[kt][2], a2f[kt][3], B.x, B.y);
                mma16816(acc[2 * np + 1], a2f[kt][0], a2f[kt][1], a2f[kt][2], a2f[kt][3], B.z, B.w);
            }
        }

        // ================= epilogue 2: +b2, SiLU, store (float4) =================
        const bool val0 = (row0 < E);
        const bool val1 = (row1 < E);
        #pragma unroll
        for (int np = 0; np < NP1; np++) {
            float4 bb = __ldg(reinterpret_cast<const float4*>(b2 + 16 * np + 4 * c4));
            float4 o0, o1;
            o0.x = silu(acc[2*np][0]   + bb.x);
            o0.y = silu(acc[2*np][1]   + bb.y);
            o0.z = silu(acc[2*np+1][0] + bb.z);
            o0.w = silu(acc[2*np+1][1] + bb.w);
            o1.x = silu(acc[2*np][2]   + bb.x);
            o1.y = silu(acc[2*np][3]   + bb.y);
            o1.z = silu(acc[2*np+1][2] + bb.z);
            o1.w = silu(acc[2*np+1][3] + bb.w);
            const int col = 16 * np + 4 * c4;
            if (val0) *reinterpret_cast<float4*>(out + (size_t)row0 * 128 + col) = o0;
            if (val1) *reinterpret_cast<float4*>(out + (size_t)row1 * 128 + col) = o1;
        }
    }
}

// ===================== launch =====================
extern "C" void kernel_launch(void* const* d_in, const int* in_sizes, int n_in,
                              void* d_out, int out_size)
{
    (void)n_in; (void)out_size;
    const float* src = (const float*)d_in[0];
    const float* edg = (const float*)d_in[1];
    const float* W1  = (const float*)d_in[2];
    const float* b1  = (const float*)d_in[3];
    const float* gma = (const float*)d_in[4];
    const float* bta = (const float*)d_in[5];
    const float* W2  = (const float*)d_in[6];
    const float* b2  = (const float*)d_in[7];
    float* out = (float*)d_out;

    const int E = in_sizes[0] / 128;
    const int n_groups = (E + 15) / 16;

    cudaFuncSetAttribute(edge_mlp_kernel,
                         cudaFuncAttributeMaxDynamicSharedMemorySize, SMEM_BYTES);
    edge_mlp_kernel<<<304, 256, SMEM_BYTES>>>(src, edg, W1, b1, gma, bta, W2, b2,
                                              out, E, n_groups);
}